// round 14
// baseline (speedup 1.0000x reference)
#include <cuda_runtime.h>
#include <math.h>

// grid_layer, two kernels.
//  K1: per-(node,neighbor) great-circle (dist,phi). PRECISE sinf/cosf
//      (R12 showed __sincosf -> acosf amplification costs 1e-4 rel_err).
//      Separately-rounded products so the self-pair gives atan2(+0,+0)=+0
//      (bit-matches XLA; FMA contraction was the sqrt(1/7) bug).
//  K2: one warp per node, lane = (t_i, e4):  t_i = lane>>2 (8 thetas),
//      e4 = lane&3 (feature quad). Each lane computes all 4 d-cells for its
//      (t_i, e4) -> needs only 7 float4 smem reads (vs 28 in the old (d,t)
//      mapping). Broadcast LDS.128 costs 4 wavefronts regardless of address
//      uniqueness (R11 calibration), so this cuts the dominant L1 term 4x.

#define PI_F 3.14159265358979323846f
#define FULL 0xffffffffu
#define MAXN 65536

__device__ float2 g_dp[MAXN * 7];   // (dist, phi) per (node, neighbor)

// ---------------- Kernel 1: precise trig, one thread per (node, k) ----------
__global__ __launch_bounds__(256) void trig_kernel(
    const float* __restrict__ coords,      // [2, N]
    const int*   __restrict__ local_indices,
    const int*   __restrict__ adjc,        // [N, 7]
    int N)
{
    const int t = blockIdx.x * 256 + threadIdx.x;
    if (t >= N * 7) return;
    const int node = t / 7;
    const int k    = t - node * 7;

    const int li   = __ldg(&local_indices[node]);
    const int idx0 = __ldg(&adjc[li * 7]);
    const int idxk = __ldg(&adjc[li * 7 + k]);

    const float lon1 = __ldg(&coords[idx0]);
    const float lat1 = __ldg(&coords[N + idx0]);
    const float lon2 = __ldg(&coords[idxk]);
    const float lat2 = __ldg(&coords[N + idxk]);
    const float dlon = lon2 - lon1;

    const float s1 = sinf(lat1), c1 = cosf(lat1);
    const float s2 = sinf(lat2), c2 = cosf(lat2);
    const float sd = sinf(dlon), cd = cosf(dlon);

    // separately rounded, matching XLA's elementwise lowering
    float cosd = __fadd_rn(__fmul_rn(s1, s2),
                           __fmul_rn(__fmul_rn(c1, c2), cd));
    cosd = fminf(fmaxf(cosd, -1.0f + 1e-7f), 1.0f - 1e-7f);

    const float yy = __fsub_rn(__fmul_rn(c1, s2),
                               __fmul_rn(__fmul_rn(s1, c2), cd));
    const float xx = __fmul_rn(sd, c2);

    g_dp[t] = make_float2(acosf(cosd), atan2f(xx, yy));
}

// ---------------- Kernel 2: weights + gather + store, one warp per node ----
__global__ __launch_bounds__(256) void project_kernel(
    const float* __restrict__ x,
    const float* __restrict__ sigma_d_p,
    const float* __restrict__ kappa_p,
    const int*   __restrict__ local_indices,
    const int*   __restrict__ adjc,
    float*       __restrict__ out,         // [N, 4, 8, 16]
    int N)
{
    __shared__ float xs[8][116];           // per warp: 7 rows x 16 feats (+pad)

    const int warp = threadIdx.x >> 5;
    const int lane = threadIdx.x & 31;
    const int node = blockIdx.x * 8 + warp;
    if (node >= N) return;

    // --- neighbor indices: speculate li == node (loads overlap) ---
    int idxk = 0;
    if (lane < 7) idxk = __ldg(&adjc[node * 7 + lane]);     // speculative
    const int li = __ldg(&local_indices[node]);
    if (li != node) {                                        // warp-uniform
        if (lane < 7) idxk = __ldg(&adjc[li * 7 + lane]);
    }

    // --- dist/phi: 56B contiguous -> lanes 0..13, then shfl broadcast ---
    float dpv = 0.0f;
    if (lane < 14) dpv = __ldg(reinterpret_cast<const float*>(g_dp) + node * 14 + lane);

    // --- x rows: 28 lanes, one LDG.128 each (7x64B), stage to smem ---
    const int xi = __shfl_sync(FULL, idxk, lane >> 2);
    if (lane < 28) {
        const float4 v = __ldg(reinterpret_cast<const float4*>(
            x + (size_t)xi * 16) + (lane & 3));
        *reinterpret_cast<float4*>(&xs[warp][(lane >> 2) * 16 + (lane & 3) * 4]) = v;
    }

    float dist[7], phi[7];
#pragma unroll
    for (int k = 0; k < 7; k++) {
        dist[k] = __shfl_sync(FULL, dpv, 2 * k);
        phi[k]  = __shfl_sync(FULL, dpv, 2 * k + 1);
    }
    __syncwarp();

    const float inv_sigma = 1.0f / __ldg(&sigma_d_p[0]);
    const float kappa     = __ldg(&kappa_p[0]);

    // lane mapping: t_i = lane>>2 (theta), e4 = lane&3 (feature quad)
    const int t_i = lane >> 2;
    const int e4  = lane & 3;
    const float theta = -PI_F + (float)t_i * (PI_F * 0.25f);

    // weights for all 4 d-cells of this theta (fused fast-math exp)
    float w[4][7];
    float sum0 = 0.f, sum1 = 0.f, sum2 = 0.f, sum3 = 0.f;
#pragma unroll
    for (int k = 0; k < 7; k++) {
        const float ck = kappa * __cosf(theta - phi[k]);
#pragma unroll
        for (int d = 0; d < 4; d++) {
            const float z = ((float)d * (0.2f / 3.0f) - dist[k]) * inv_sigma;
            w[d][k] = __expf(ck - 0.5f * z * z);
        }
        sum0 += w[0][k]; sum1 += w[1][k]; sum2 += w[2][k]; sum3 += w[3][k];
    }
    const float inv0 = 1.0f / (sum0 + 1e-10f);
    const float inv1 = 1.0f / (sum1 + 1e-10f);
    const float inv2 = 1.0f / (sum2 + 1e-10f);
    const float inv3 = 1.0f / (sum3 + 1e-10f);

    // weighted feature sum: only 7 smem float4 reads per lane (its e4 chunk)
    float4 a0 = make_float4(0.f, 0.f, 0.f, 0.f);
    float4 a1 = a0, a2 = a0, a3 = a0;
    const float* xw = xs[warp];
#pragma unroll
    for (int k = 0; k < 7; k++) {
        const float4 v = *reinterpret_cast<const float4*>(xw + k * 16 + e4 * 4);
        const float w0 = w[0][k] * inv0;
        const float w1 = w[1][k] * inv1;
        const float w2 = w[2][k] * inv2;
        const float w3 = w[3][k] * inv3;
        a0.x += w0 * v.x; a0.y += w0 * v.y; a0.z += w0 * v.z; a0.w += w0 * v.w;
        a1.x += w1 * v.x; a1.y += w1 * v.y; a1.z += w1 * v.z; a1.w += w1 * v.w;
        a2.x += w2 * v.x; a2.y += w2 * v.y; a2.z += w2 * v.z; a2.w += w2 * v.w;
        a3.x += w3 * v.x; a3.y += w3 * v.y; a3.z += w3 * v.z; a3.w += w3 * v.w;
    }

    // stores: per d the warp writes 512B contiguous (t_i*16 + e4*4)
    float* o = out + (size_t)node * 512 + t_i * 16 + e4 * 4;
    *reinterpret_cast<float4*>(o + 0)   = a0;
    *reinterpret_cast<float4*>(o + 128) = a1;
    *reinterpret_cast<float4*>(o + 256) = a2;
    *reinterpret_cast<float4*>(o + 384) = a3;
}

extern "C" void kernel_launch(void* const* d_in, const int* in_sizes, int n_in,
                              void* d_out, int out_size) {
    const int N = out_size / 512;   // out is (1, N, 4, 8, 16)

    // Bind inputs by element count (robust to metadata ordering).
    const float* x       = 0;
    const float* coords  = 0;
    const float* sigma_d = 0;
    const float* kappa   = 0;
    const int*   lidx    = 0;
    const int*   adjc    = 0;
    int n_scalar = 0;
    for (int i = 0; i < n_in; i++) {
        const int s = in_sizes[i];
        if (s == 1) {
            if (n_scalar++ == 0) sigma_d = (const float*)d_in[i];
            else                 kappa   = (const float*)d_in[i];
        } else if (s == N)        lidx   = (const int*)d_in[i];
        else if (s == 2 * N)      coords = (const float*)d_in[i];
        else if (s == 7 * N)      adjc   = (const int*)d_in[i];
        else if (s == 16 * N)     x      = (const float*)d_in[i];
    }

    float* out = (float*)d_out;

    const int t1 = N * 7;
    trig_kernel<<<(t1 + 255) / 256, 256>>>(coords, lidx, adjc, N);
    project_kernel<<<(N + 7) / 8, 256>>>(x, sigma_d, kappa, lidx, adjc, out, N);
}

// round 16
// speedup vs baseline: 1.9233x; 1.9233x over previous
#include <cuda_runtime.h>
#include <math.h>

// grid_layer, two kernels.
//  K1: per-(node,neighbor) great-circle (dist,phi). PRECISE sinf/cosf
//      (R12: __sincosf->acosf amplification costs 1e-4). Separately-rounded
//      products so the self-pair gives atan2(+0,+0)=+0 (bit-matches XLA;
//      FMA contraction was the sqrt(1/7) bug).
//  K2 hybrid (R11 x R13 lesson):
//      producer lanes (d,t) compute 7 fused exps + normalize  (compute-min)
//      consumer lanes (t,e4) read 7 LDS.128 + 28 weight-SHFLs (memory-min)
//      -> per-warp L1 wavefronts ~56 (vs 140 in R11), exps stay 7/lane.

#define PI_F 3.14159265358979323846f
#define FULL 0xffffffffu
#define MAXN 65536

__device__ float2 g_dp[MAXN * 7];   // (dist, phi) per (node, neighbor)

// ---------------- Kernel 1: precise trig, one thread per (node, k) ----------
__global__ __launch_bounds__(256) void trig_kernel(
    const float* __restrict__ coords,      // [2, N]
    const int*   __restrict__ local_indices,
    const int*   __restrict__ adjc,        // [N, 7]
    int N)
{
    const int t = blockIdx.x * 256 + threadIdx.x;
    if (t >= N * 7) return;
    const int node = t / 7;
    const int k    = t - node * 7;

    const int li   = __ldg(&local_indices[node]);
    const int idx0 = __ldg(&adjc[li * 7]);
    const int idxk = __ldg(&adjc[li * 7 + k]);

    const float lon1 = __ldg(&coords[idx0]);
    const float lat1 = __ldg(&coords[N + idx0]);
    const float lon2 = __ldg(&coords[idxk]);
    const float lat2 = __ldg(&coords[N + idxk]);
    const float dlon = lon2 - lon1;

    const float s1 = sinf(lat1), c1 = cosf(lat1);
    const float s2 = sinf(lat2), c2 = cosf(lat2);
    const float sd = sinf(dlon), cd = cosf(dlon);

    // separately rounded, matching XLA's elementwise lowering
    float cosd = __fadd_rn(__fmul_rn(s1, s2),
                           __fmul_rn(__fmul_rn(c1, c2), cd));
    cosd = fminf(fmaxf(cosd, -1.0f + 1e-7f), 1.0f - 1e-7f);

    const float yy = __fsub_rn(__fmul_rn(c1, s2),
                               __fmul_rn(__fmul_rn(s1, c2), cd));
    const float xx = __fmul_rn(sd, c2);

    g_dp[t] = make_float2(acosf(cosd), atan2f(xx, yy));
}

// ---------------- Kernel 2: hybrid weights/gather/store, 1 warp per node ---
__global__ __launch_bounds__(256) void project_kernel(
    const float* __restrict__ x,
    const float* __restrict__ sigma_d_p,
    const float* __restrict__ kappa_p,
    const int*   __restrict__ local_indices,
    const int*   __restrict__ adjc,
    float*       __restrict__ out,         // [N, 4, 8, 16]
    int N)
{
    __shared__ float xs[8][116];           // per warp: 7 rows x 16 feats (+pad)

    const int warp = threadIdx.x >> 5;
    const int lane = threadIdx.x & 31;
    const int node = blockIdx.x * 8 + warp;
    if (node >= N) return;

    // --- neighbor indices: speculate li == node (loads overlap) ---
    int idxk = 0;
    if (lane < 7) idxk = __ldg(&adjc[node * 7 + lane]);     // speculative
    const int li = __ldg(&local_indices[node]);
    if (li != node) {                                        // warp-uniform
        if (lane < 7) idxk = __ldg(&adjc[li * 7 + lane]);
    }

    // --- dist/phi: 56B contiguous -> lanes 0..13, then shfl broadcast ---
    float dpv = 0.0f;
    if (lane < 14) dpv = __ldg(reinterpret_cast<const float*>(g_dp) + node * 14 + lane);

    // --- x rows: 28 lanes, one LDG.128 each (7x64B), stage to smem ---
    const int xi = __shfl_sync(FULL, idxk, lane >> 2);
    if (lane < 28) {
        const float4 v = __ldg(reinterpret_cast<const float4*>(
            x + (size_t)xi * 16) + (lane & 3));
        *reinterpret_cast<float4*>(&xs[warp][(lane >> 2) * 16 + (lane & 3) * 4]) = v;
    }

    float dist[7], phi[7];
#pragma unroll
    for (int k = 0; k < 7; k++) {
        dist[k] = __shfl_sync(FULL, dpv, 2 * k);
        phi[k]  = __shfl_sync(FULL, dpv, 2 * k + 1);
    }

    const float inv_sigma = 1.0f / __ldg(&sigma_d_p[0]);
    const float kappa     = __ldg(&kappa_p[0]);

    // ---- producer role: this lane = (d_i, t_i) grid cell ----
    const int d_i = lane >> 3;
    const int t_i = lane & 7;
    const float dpos  = (float)d_i * (0.2f / 3.0f);          // linspace(0,0.2,4)
    const float theta = -PI_F + (float)t_i * (PI_F * 0.25f); // linspace(-pi,pi,9)[:-1]

    float wn[7];
    float sum = 0.0f;
#pragma unroll
    for (int k = 0; k < 7; k++) {
        const float z   = (dpos - dist[k]) * inv_sigma;
        const float arg = __fmaf_rn(kappa, __cosf(theta - phi[k]),
                                    -0.5f * z * z);
        wn[k] = __expf(arg);
        sum += wn[k];
    }
    const float inv = 1.0f / (sum + 1e-10f);
#pragma unroll
    for (int k = 0; k < 7; k++) wn[k] *= inv;

    __syncwarp();   // xs staged before consumer reads

    // ---- consumer role: this lane = (t_c, e4) ----
    const int t_c = lane >> 2;                 // theta index 0..7
    const int e4  = lane & 3;                  // feature quad 0..3

    float4 a0 = make_float4(0.f, 0.f, 0.f, 0.f);
    float4 a1 = a0, a2 = a0, a3 = a0;
    const float* xw = xs[warp];
#pragma unroll
    for (int k = 0; k < 7; k++) {
        const float4 v = *reinterpret_cast<const float4*>(xw + k * 16 + e4 * 4);
        // normalized weights for (d, t_c) live in producer lanes d*8 + t_c
        const float w0 = __shfl_sync(FULL, wn[k], t_c);
        const float w1 = __shfl_sync(FULL, wn[k], 8 + t_c);
        const float w2 = __shfl_sync(FULL, wn[k], 16 + t_c);
        const float w3 = __shfl_sync(FULL, wn[k], 24 + t_c);
        a0.x += w0 * v.x; a0.y += w0 * v.y; a0.z += w0 * v.z; a0.w += w0 * v.w;
        a1.x += w1 * v.x; a1.y += w1 * v.y; a1.z += w1 * v.z; a1.w += w1 * v.w;
        a2.x += w2 * v.x; a2.y += w2 * v.y; a2.z += w2 * v.z; a2.w += w2 * v.w;
        a3.x += w3 * v.x; a3.y += w3 * v.y; a3.z += w3 * v.z; a3.w += w3 * v.w;
    }

    // stores: per d the warp writes 512B contiguous (t_c*16 + e4*4)
    float* o = out + (size_t)node * 512 + t_c * 16 + e4 * 4;
    *reinterpret_cast<float4*>(o + 0)   = a0;
    *reinterpret_cast<float4*>(o + 128) = a1;
    *reinterpret_cast<float4*>(o + 256) = a2;
    *reinterpret_cast<float4*>(o + 384) = a3;
}

extern "C" void kernel_launch(void* const* d_in, const int* in_sizes, int n_in,
                              void* d_out, int out_size) {
    const int N = out_size / 512;   // out is (1, N, 4, 8, 16)

    // Bind inputs by element count (robust to metadata ordering).
    const float* x       = 0;
    const float* coords  = 0;
    const float* sigma_d = 0;
    const float* kappa   = 0;
    const int*   lidx    = 0;
    const int*   adjc    = 0;
    int n_scalar = 0;
    for (int i = 0; i < n_in; i++) {
        const int s = in_sizes[i];
        if (s == 1) {
            if (n_scalar++ == 0) sigma_d = (const float*)d_in[i];
            else                 kappa   = (const float*)d_in[i];
        } else if (s == N)        lidx   = (const int*)d_in[i];
        else if (s == 2 * N)      coords = (const float*)d_in[i];
        else if (s == 7 * N)      adjc   = (const int*)d_in[i];
        else if (s == 16 * N)     x      = (const float*)d_in[i];
    }

    float* out = (float*)d_out;

    const int t1 = N * 7;
    trig_kernel<<<(t1 + 255) / 256, 256>>>(coords, lidx, adjc, N);
    project_kernel<<<(N + 7) / 8, 256>>>(x, sigma_d, kappa, lidx, adjc, out, N);
}

// round 17
// speedup vs baseline: 2.1389x; 1.1121x over previous
#include <cuda_runtime.h>
#include <math.h>

// grid_layer, three kernels.
//  K1a: per-node precise sincos(lat), sincos(lon) -> float4 table.
//  K1b: per-(node,k) dist/phi from the table via angle-difference identities
//       (no sin/cos), separately-rounded products. Self-pair (idxk==idx0)
//       branch reproduces the XLA reference bit pattern exactly:
//       cosd = fl(s1^2)+fl(c1^2), phi = +0.  (atan2 sign near the degenerate
//       pair was the sqrt(1/7) bug class; never leave it to rounding luck.)
//  K2:  one warp per node. Producer lanes (t,d)=(lane>>2,lane&3) compute 7
//       fused exps + normalize; weights transposed through smem so consumer
//       lanes (t,e4) fetch 4 d-weights with ONE LDS.128 per k (replaces 28
//       SHFLs -- SHFL shares the MIO pipe, R15 lesson). Consumers read 7
//       x-quads from smem, write 4 float4 (contiguous 512B per d).

#define PI_F 3.14159265358979323846f
#define FULL 0xffffffffu
#define MAXN 65536

__device__ float2 g_dp[MAXN * 7];   // (dist, phi) per (node, neighbor)
__device__ float4 g_sc[MAXN];       // (sin lat, cos lat, sin lon, cos lon)

// ---------------- Kernel 1a: per-node sincos table --------------------------
__global__ __launch_bounds__(256) void sincos_kernel(
    const float* __restrict__ coords,      // [2, N]
    int N)
{
    const int node = blockIdx.x * 256 + threadIdx.x;
    if (node >= N) return;
    const float lon = __ldg(&coords[node]);
    const float lat = __ldg(&coords[N + node]);
    g_sc[node] = make_float4(sinf(lat), cosf(lat), sinf(lon), cosf(lon));
}

// ---------------- Kernel 1b: dist/phi, one thread per (node, k) -------------
__global__ __launch_bounds__(256) void trig_kernel(
    const int* __restrict__ local_indices,
    const int* __restrict__ adjc,          // [N, 7]
    int N)
{
    const int t = blockIdx.x * 256 + threadIdx.x;
    if (t >= N * 7) return;
    const int node = t / 7;
    const int k    = t - node * 7;

    const int li   = __ldg(&local_indices[node]);
    const int idx0 = __ldg(&adjc[li * 7]);
    const int idxk = __ldg(&adjc[li * 7 + k]);

    const float4 A = __ldg(&g_sc[idx0]);   // s1, c1, sl1, cl1
    const float4 B = __ldg(&g_sc[idxk]);   // s2, c2, sl2, cl2

    float dist, ph;
    if (idxk == idx0) {
        // exact reference bit pattern: cd = cosf(0) = 1
        float cosd = __fadd_rn(__fmul_rn(A.x, A.x), __fmul_rn(A.y, A.y));
        cosd = fminf(fmaxf(cosd, -1.0f + 1e-7f), 1.0f - 1e-7f);
        dist = acosf(cosd);
        ph   = 0.0f;
    } else {
        // sin/cos(lon2-lon1) via identities (separately rounded)
        const float sd = __fsub_rn(__fmul_rn(B.z, A.w), __fmul_rn(B.w, A.z));
        float cd = __fadd_rn(__fmul_rn(B.w, A.w), __fmul_rn(B.z, A.z));
        cd = fminf(cd, 1.0f);              // guard: never exceed cos(0)

        float cosd = __fadd_rn(__fmul_rn(A.x, B.x),
                               __fmul_rn(__fmul_rn(A.y, B.y), cd));
        cosd = fminf(fmaxf(cosd, -1.0f + 1e-7f), 1.0f - 1e-7f);

        const float yy = __fsub_rn(__fmul_rn(A.y, B.x),
                                   __fmul_rn(__fmul_rn(A.x, B.y), cd));
        const float xx = __fmul_rn(sd, B.y);
        dist = acosf(cosd);
        ph   = atan2f(xx, yy);
    }
    g_dp[t] = make_float2(dist, ph);
}

// ---------------- Kernel 2: weights + gather + store, 1 warp per node -------
__global__ __launch_bounds__(256) void project_kernel(
    const float* __restrict__ x,
    const float* __restrict__ sigma_d_p,
    const float* __restrict__ kappa_p,
    const int*   __restrict__ local_indices,
    const int*   __restrict__ adjc,
    float*       __restrict__ out,         // [N, 4, 8, 16]
    int N)
{
    __shared__ __align__(16) float xs[8][116];     // 7 rows x 16 feats (+pad)
    __shared__ __align__(16) float ws[8][7][32];   // weights, lane=(t*4+d)

    const int warp = threadIdx.x >> 5;
    const int lane = threadIdx.x & 31;
    const int node = blockIdx.x * 8 + warp;
    if (node >= N) return;

    // --- neighbor indices: speculate li == node (loads overlap) ---
    int idxk = 0;
    if (lane < 7) idxk = __ldg(&adjc[node * 7 + lane]);     // speculative
    const int li = __ldg(&local_indices[node]);
    if (li != node) {                                        // warp-uniform
        if (lane < 7) idxk = __ldg(&adjc[li * 7 + lane]);
    }

    // --- dist/phi: 56B contiguous -> lanes 0..13, then shfl broadcast ---
    float dpv = 0.0f;
    if (lane < 14) dpv = __ldg(reinterpret_cast<const float*>(g_dp) + node * 14 + lane);

    // --- x rows: 28 lanes, one LDG.128 each (7x64B), stage to smem ---
    const int xi = __shfl_sync(FULL, idxk, lane >> 2);
    if (lane < 28) {
        const float4 v = __ldg(reinterpret_cast<const float4*>(
            x + (size_t)xi * 16) + (lane & 3));
        *reinterpret_cast<float4*>(&xs[warp][(lane >> 2) * 16 + (lane & 3) * 4]) = v;
    }

    float dist[7], phi[7];
#pragma unroll
    for (int k = 0; k < 7; k++) {
        dist[k] = __shfl_sync(FULL, dpv, 2 * k);
        phi[k]  = __shfl_sync(FULL, dpv, 2 * k + 1);
    }

    const float inv_sigma = 1.0f / __ldg(&sigma_d_p[0]);
    const float kappa     = __ldg(&kappa_p[0]);

    // ---- producer role: lane = (t_p, d_p) = (lane>>2, lane&3) ----
    const float dpos  = (float)(lane & 3) * (0.2f / 3.0f);
    const float theta = -PI_F + (float)(lane >> 2) * (PI_F * 0.25f);

    float wn[7];
    float sum = 0.0f;
#pragma unroll
    for (int k = 0; k < 7; k++) {
        const float z   = (dpos - dist[k]) * inv_sigma;
        const float arg = __fmaf_rn(kappa, __cosf(theta - phi[k]),
                                    -0.5f * z * z);
        wn[k] = __expf(arg);
        sum += wn[k];
    }
    const float inv = 1.0f / (sum + 1e-10f);
#pragma unroll
    for (int k = 0; k < 7; k++) ws[warp][k][lane] = wn[k] * inv;  // 7 coalesced STS

    __syncwarp();   // xs + ws staged before consumer reads

    // ---- consumer role: lane = (t_c, e4) ----
    const int t_c = lane >> 2;                 // theta index 0..7
    const int e4  = lane & 3;                  // feature quad 0..3

    float4 a0 = make_float4(0.f, 0.f, 0.f, 0.f);
    float4 a1 = a0, a2 = a0, a3 = a0;
    const float* xw = xs[warp];
#pragma unroll
    for (int k = 0; k < 7; k++) {
        const float4 v  = *reinterpret_cast<const float4*>(xw + k * 16 + e4 * 4);
        const float4 w4 = *reinterpret_cast<const float4*>(&ws[warp][k][t_c * 4]);
        a0.x += w4.x * v.x; a0.y += w4.x * v.y; a0.z += w4.x * v.z; a0.w += w4.x * v.w;
        a1.x += w4.y * v.x; a1.y += w4.y * v.y; a1.z += w4.y * v.z; a1.w += w4.y * v.w;
        a2.x += w4.z * v.x; a2.y += w4.z * v.y; a2.z += w4.z * v.z; a2.w += w4.z * v.w;
        a3.x += w4.w * v.x; a3.y += w4.w * v.y; a3.z += w4.w * v.z; a3.w += w4.w * v.w;
    }

    // stores: per d the warp writes 512B contiguous (t_c*16 + e4*4)
    float* o = out + (size_t)node * 512 + t_c * 16 + e4 * 4;
    *reinterpret_cast<float4*>(o + 0)   = a0;
    *reinterpret_cast<float4*>(o + 128) = a1;
    *reinterpret_cast<float4*>(o + 256) = a2;
    *reinterpret_cast<float4*>(o + 384) = a3;
}

extern "C" void kernel_launch(void* const* d_in, const int* in_sizes, int n_in,
                              void* d_out, int out_size) {
    const int N = out_size / 512;   // out is (1, N, 4, 8, 16)

    // Bind inputs by element count (robust to metadata ordering).
    const float* x       = 0;
    const float* coords  = 0;
    const float* sigma_d = 0;
    const float* kappa   = 0;
    const int*   lidx    = 0;
    const int*   adjc    = 0;
    int n_scalar = 0;
    for (int i = 0; i < n_in; i++) {
        const int s = in_sizes[i];
        if (s == 1) {
            if (n_scalar++ == 0) sigma_d = (const float*)d_in[i];
            else                 kappa   = (const float*)d_in[i];
        } else if (s == N)        lidx   = (const int*)d_in[i];
        else if (s == 2 * N)      coords = (const float*)d_in[i];
        else if (s == 7 * N)      adjc   = (const int*)d_in[i];
        else if (s == 16 * N)     x      = (const float*)d_in[i];
    }

    float* out = (float*)d_out;

    sincos_kernel<<<(N + 255) / 256, 256>>>(coords, N);
    trig_kernel<<<(N * 7 + 255) / 256, 256>>>(lidx, adjc, N);
    project_kernel<<<(N + 7) / 8, 256>>>(x, sigma_d, kappa, lidx, adjc, out, N);
}